// round 14
// baseline (speedup 1.0000x reference)
#include <cuda_runtime.h>
#include <cstdint>

// ThresholdDecision: out[b] = 1.0f iff exists t in [1, L-CP-1] with
// x[b, t..t+CP-1, 2] > 0.5 (CP=4), else 0.0f. fp32 in, fp32 out.
//
// R13 consolidation: wall has been pinned at 6.6-6.9us across traffic
// 4.25-12.6 MB and 1-3 round-trip schedules -> fixed launch/scheduling floor
// dominates (timed loop is warm-L2; cold ncu favored the small first chunk).
// This round: (a) 256 blocks x 512 threads (half the CTAs to schedule),
// (b) phase A = 96 positions (traffic 4.7 MB cold, stragglers ~204 rows,
// fallback population ~0.03 rows), (c) streaming output store.

#define WARPS_PER_BLOCK 16
#define NTHREADS (WARPS_PER_BLOCK * 32)

// Scan W ballot-words (W*32 positions) starting at `base`. carry holds the
// top 3 bits of the previous word's bit-stream. Returns warp-uniform flag.
template <int W>
__device__ __forceinline__ int scan_words(const float* __restrict__ xr,
                                          int base, int L, int lane,
                                          unsigned int& carry)
{
    float v[W];
    #pragma unroll
    for (int j = 0; j < W; ++j) {
        const int p = base + j * 32 + lane;
        v[j] = (p < L) ? __ldg(&xr[(size_t)p * 3 + 2]) : 0.0f;
    }

    int found = 0;
    #pragma unroll
    for (int j = 0; j < W; ++j) {
        const int p = base + j * 32 + lane;
        // positions 0 and L-1 excluded (window t >= 1, t+3 <= L-2)
        const int pred = (v[j] > 0.5f) & (p >= 1) & (p <= L - 2);
        const unsigned int w = __ballot_sync(0xffffffffu, pred);
        const unsigned long long t = ((unsigned long long)w << 3) | carry;
        const unsigned long long r = t & (t >> 1) & (t >> 2) & (t >> 3);
        found |= (r != 0ull);
        carry = w >> 29;
    }
    return found;
}

__global__ void __launch_bounds__(NTHREADS)
threshold_decision_kernel(const float* __restrict__ x,
                          float* __restrict__ out,
                          int L, int B)
{
    const int lane = threadIdx.x & 31;
    const int warp = threadIdx.x >> 5;
    const int row  = blockIdx.x * WARPS_PER_BLOCK + warp;
    if (row >= B) return;

    const float* __restrict__ xr = x + (size_t)row * (size_t)L * 3u;

    unsigned int carry = 0u;

    // Phase A: 96 positions in one independent-load batch (one round trip).
    // P(miss) = e^-3 ~ 5% -> ~204 straggler rows.
    int found = scan_words<3>(xr, 0, L, lane, carry);

    // Phase B: +288 positions (cum 384). P(still missing) ~ e^-12.
    if (!found && L > 96)
        found = scan_words<9>(xr, 96, L, lane, carry);

    // Fallback: exhaustive 1024-position chunks (correctness on adversarial
    // data; statistically never taken on this dataset).
    for (int base = 384; !found && base < L; base += 1024)
        found = scan_words<32>(xr, base, L, lane, carry);

    if (lane == 0) __stwt(&out[row], found ? 1.0f : 0.0f);
}

extern "C" void kernel_launch(void* const* d_in, const int* in_sizes, int n_in,
                              void* d_out, int out_size)
{
    const int B = out_size;   // one flag per row

    // Select the input whose element count is divisible by B*3.
    const float* x = (const float*)d_in[0];
    long long total = in_sizes[0];
    for (int i = 0; i < n_in; ++i) {
        long long s = in_sizes[i];
        if (s >= (long long)B * 3 && s % ((long long)B * 3) == 0) {
            x = (const float*)d_in[i];
            total = s;
            break;
        }
    }
    const int L = (int)(total / ((long long)B * 3));

    const int grid = (B + WARPS_PER_BLOCK - 1) / WARPS_PER_BLOCK;
    threshold_decision_kernel<<<grid, NTHREADS>>>(x, (float*)d_out, L, B);
}